// round 7
// baseline (speedup 1.0000x reference)
#include <cuda_runtime.h>
#include <cuda_fp16.h>
#include <math.h>
#include <stdint.h>

// Problem constants (TopKRouter: B=4, S=8192, D=1024, E=64, top_k=1)
#define DK      1024
#define NE      64
#define SEQ     8192
#define CAP     640
#define MAXTOK  32768

// GEMM tiling: 256 threads = 8 warps; warp w owns rows [w*16, w*16+16) x all 64 cols
#define BM      128
#define KC      32            // K per chunk
#define KP      16            // kpairs per chunk
#define NCHUNK  (DK / KC)     // 32
#define SA      20            // A row stride in u32 words (16 kpairs + pad)
#define SB      72            // B kpair-row stride in u32 words (64 + pad)
// smem word offsets (u32 units), double-buffered stages
#define A_ST    (BM * SA)                 // 2560
#define B_ST    (KP * SB)                 // 1152
#define OFF_AH(s)  ((s) * A_ST)
#define OFF_AL(s)  (2 * A_ST + (s) * A_ST)
#define OFF_BH(s)  (4 * A_ST + (s) * B_ST)
#define OFF_BL(s)  (4 * A_ST + 2 * B_ST + (s) * B_ST)
#define SMEM_WORDS (4 * A_ST + 4 * B_ST)  // 14848
#define SMEM_REQ   (SMEM_WORDS * 4)       // 59392 B

#define FIXMAX  1024
#define FIXGRID 256
#define TIE_THRESH 1e-4f

// Scratch (no allocations allowed -> __device__ globals)
__device__ int           g_argmax[MAXTOK];
__device__ float         g_topp[MAXTOK];
__device__ unsigned char g_keep[MAXTOK];
__device__ int           g_fixn;          // zero-init; reset by scan_kernel each run
__device__ int           g_fixlist[FIXMAX];
// Pre-split W in smem layout: per chunk c, [kpair][n] with stride SB
__device__ __align__(16) uint32_t g_WH[NCHUNK * B_ST];
__device__ __align__(16) uint32_t g_WL[NCHUNK * B_ST];

__device__ __forceinline__ uint32_t smem_u32(const void* p) {
    uint32_t a;
    asm("{ .reg .u64 t; cvta.to.shared.u64 t, %1; cvt.u32.u64 %0, t; }" : "=r"(a) : "l"(p));
    return a;
}
__device__ __forceinline__ void cp16(uint32_t dst, const void* src) {
    asm volatile("cp.async.ca.shared.global [%0], [%1], 16;" :: "r"(dst), "l"(src));
}
__device__ __forceinline__ uint32_t packh2(float x, float y) {
    __half2 h = __floats2half2_rn(x, y);
    return *(uint32_t*)&h;
}
__device__ __forceinline__ void split_pair(float x, float y, uint32_t& hi, uint32_t& lo) {
    float hx = __half2float(__float2half_rn(x));
    float hy = __half2float(__float2half_rn(y));
    hi = packh2(hx, hy);
    lo = packh2(x - hx, y - hy);
}
__device__ __forceinline__ void mma16(float* d,
                                      uint32_t a0, uint32_t a1, uint32_t a2, uint32_t a3,
                                      uint32_t b0, uint32_t b1) {
    asm volatile(
        "mma.sync.aligned.m16n8k16.row.col.f32.f16.f16.f32 "
        "{%0,%1,%2,%3}, {%4,%5,%6,%7}, {%8,%9}, {%0,%1,%2,%3};"
        : "+f"(d[0]), "+f"(d[1]), "+f"(d[2]), "+f"(d[3])
        : "r"(a0), "r"(a1), "r"(a2), "r"(a3), "r"(b0), "r"(b1));
}

// ---------------------------------------------------------------------------
// Kernel 0: pre-split W (fp32 -> fp16 hi/lo) into chunk-major padded layout.
// ---------------------------------------------------------------------------
__global__ __launch_bounds__(256)
void prep_W(const float* __restrict__ W)
{
    const int c = blockIdx.x;                 // chunk 0..31
    for (int i = threadIdx.x; i < NE * KP; i += 256) {
        const int n  = i >> 4;                // 0..63 (consecutive threads: same n? no -> i&15 kp)
        const int kp = i & 15;                // coalesced reads over kp
        float2 v = *(const float2*)(W + (size_t)n * DK + c * KC + kp * 2);
        uint32_t hi, lo;
        split_pair(v.x, v.y, hi, lo);
        g_WH[c * B_ST + kp * SB + n] = hi;
        g_WL[c * B_ST + kp * SB + n] = lo;
    }
}

// ---------------------------------------------------------------------------
// Kernel 1: logits = x @ W^T via mma.sync fp16 2-term-split (3 passes),
// double-buffered smem, cp.async B tiles, 1 sync per chunk. Fused top-1
// softmax epilogue; near-tie tokens queued for exact fp32 fixup.
// ---------------------------------------------------------------------------
__global__ __launch_bounds__(256, 2)
void gemm_router_mma(const float* __restrict__ x,
                     float* __restrict__ logits,
                     int*   __restrict__ amax,
                     float* __restrict__ topp)
{
    extern __shared__ uint32_t smw[];
    const uint32_t smb = smem_u32(smw);

    const int tid  = threadIdx.x;
    const int wid  = tid >> 5;
    const int lane = tid & 31;
    const int l4   = lane >> 2;     // 0..7
    const int lc   = lane & 3;      // 0..3
    const int wm   = wid * 16;
    const int m0   = blockIdx.x * BM;

    // A loader: 8 threads per row, 4 rows per pass q (rows arow+32q)
    const int arow = tid >> 3;      // 0..31
    const int ac4  = tid & 7;       // float4 slot within 32-float row chunk

    const float* xb = x + (size_t)m0 * DK;

    float acc[8][4];
    #pragma unroll
    for (int j = 0; j < 8; j++)
        #pragma unroll
        for (int t = 0; t < 4; t++) acc[j][t] = 0.0f;

    float4 pa[4];

    // ---- prologue: chunk 0 into stage 0 ----
    #pragma unroll
    for (int q = 0; q < 4; q++)
        pa[q] = *(const float4*)(xb + (size_t)(arow + 32 * q) * DK + ac4 * 4);
    for (int i = tid; i < B_ST / 4; i += 256) {
        cp16(smb + (OFF_BH(0) + i * 4) * 4, g_WH + i * 4);
        cp16(smb + (OFF_BL(0) + i * 4) * 4, g_WL + i * 4);
    }
    asm volatile("cp.async.commit_group;");
    #pragma unroll
    for (int q = 0; q < 4; q++) {
        const int row = arow + 32 * q;
        uint32_t h0, l0, h1, l1;
        split_pair(pa[q].x, pa[q].y, h0, l0);
        split_pair(pa[q].z, pa[q].w, h1, l1);
        *(uint2*)(smw + OFF_AH(0) + row * SA + ac4 * 2) = make_uint2(h0, h1);
        *(uint2*)(smw + OFF_AL(0) + row * SA + ac4 * 2) = make_uint2(l0, l1);
    }
    // prefetch A(1)
    #pragma unroll
    for (int q = 0; q < 4; q++)
        pa[q] = *(const float4*)(xb + (size_t)(arow + 32 * q) * DK + KC + ac4 * 4);
    asm volatile("cp.async.wait_group 0;");
    __syncthreads();

    for (int c = 0; c < NCHUNK; c++) {
        const int s  = c & 1;
        const int sn = s ^ 1;

        if (c + 1 < NCHUNK) {
            // cp.async B(c+1) -> stage sn
            const uint32_t* WHs = g_WH + (c + 1) * B_ST;
            const uint32_t* WLs = g_WL + (c + 1) * B_ST;
            for (int i = tid; i < B_ST / 4; i += 256) {
                cp16(smb + (OFF_BH(sn) + i * 4) * 4, WHs + i * 4);
                cp16(smb + (OFF_BL(sn) + i * 4) * 4, WLs + i * 4);
            }
            asm volatile("cp.async.commit_group;");
            // STS A(c+1) -> stage sn
            #pragma unroll
            for (int q = 0; q < 4; q++) {
                const int row = arow + 32 * q;
                uint32_t h0, l0, h1, l1;
                split_pair(pa[q].x, pa[q].y, h0, l0);
                split_pair(pa[q].z, pa[q].w, h1, l1);
                *(uint2*)(smw + OFF_AH(sn) + row * SA + ac4 * 2) = make_uint2(h0, h1);
                *(uint2*)(smw + OFF_AL(sn) + row * SA + ac4 * 2) = make_uint2(l0, l1);
            }
            // LDG A(c+2)
            if (c + 2 < NCHUNK) {
                const int k0 = (c + 2) * KC;
                #pragma unroll
                for (int q = 0; q < 4; q++)
                    pa[q] = *(const float4*)(xb + (size_t)(arow + 32 * q) * DK + k0 + ac4 * 4);
            }
        }

        // ---- MMA on stage s: 2 k16-steps x 8 n-tiles x 3 passes ----
        const uint32_t* Ah = smw + OFF_AH(s);
        const uint32_t* Al = smw + OFF_AL(s);
        const uint32_t* Bh = smw + OFF_BH(s);
        const uint32_t* Bl = smw + OFF_BL(s);
        #pragma unroll
        for (int ks = 0; ks < 2; ks++) {
            const int ko = ks * 8;
            const int ai = (wm + l4) * SA + ko + lc;
            uint32_t ah0 = Ah[ai],     ah1 = Ah[ai + 8 * SA];
            uint32_t ah2 = Ah[ai + 4], ah3 = Ah[ai + 8 * SA + 4];
            uint32_t al0 = Al[ai],     al1 = Al[ai + 8 * SA];
            uint32_t al2 = Al[ai + 4], al3 = Al[ai + 8 * SA + 4];
            const int bi = (ko + lc) * SB + l4;
            #pragma unroll
            for (int j = 0; j < 8; j++) {
                uint32_t bh0 = Bh[bi + j * 8], bh1 = Bh[bi + 4 * SB + j * 8];
                uint32_t bl0 = Bl[bi + j * 8], bl1 = Bl[bi + 4 * SB + j * 8];
                mma16(acc[j], ah0, ah1, ah2, ah3, bh0, bh1);  // hi*hi
                mma16(acc[j], ah0, ah1, ah2, ah3, bl0, bl1);  // hi*lo
                mma16(acc[j], al0, al1, al2, al3, bh0, bh1);  // lo*hi
            }
        }
        if (c + 1 < NCHUNK) asm volatile("cp.async.wait_group 0;");
        __syncthreads();
    }

    // ---- Epilogue: c0/c1 -> row wm+l4, c2/c3 -> row wm+l4+8; cols j*8+2lc(+1)
    #pragma unroll
    for (int half = 0; half < 2; half++) {
        const int r = m0 + wm + l4 + 8 * half;

        #pragma unroll
        for (int j = 0; j < 8; j++) {
            *(float2*)&logits[(size_t)r * NE + j * 8 + 2 * lc] =
                make_float2(acc[j][2 * half], acc[j][2 * half + 1]);
        }
        // local top1/top2 (+index)
        float m1 = -1e30f, m2 = -1e30f; int i1 = 0;
        #pragma unroll
        for (int j = 0; j < 8; j++)
            #pragma unroll
            for (int t = 0; t < 2; t++) {
                float v = acc[j][2 * half + t];
                int col = j * 8 + 2 * lc + t;
                if (v > m1) { m2 = m1; m1 = v; i1 = col; }
                else if (v > m2) m2 = v;
            }
        // quad merge (lanes sharing l4)
        #pragma unroll
        for (int off = 1; off <= 2; off <<= 1) {
            float om1 = __shfl_xor_sync(0xffffffffu, m1, off);
            int   oi1 = __shfl_xor_sync(0xffffffffu, i1, off);
            float om2 = __shfl_xor_sync(0xffffffffu, m2, off);
            if (om1 > m1 || (om1 == m1 && oi1 < i1)) {
                m2 = fmaxf(m1, om2); m1 = om1; i1 = oi1;
            } else {
                m2 = fmaxf(m2, om1);
            }
        }
        // softmax sum with converged max
        float s = 0.0f;
        #pragma unroll
        for (int j = 0; j < 8; j++)
            #pragma unroll
            for (int t = 0; t < 2; t++)
                s += __expf(acc[j][2 * half + t] - m1);
        s += __shfl_xor_sync(0xffffffffu, s, 1);
        s += __shfl_xor_sync(0xffffffffu, s, 2);

        if (lc == 0) {
            amax[r] = i1;
            topp[r] = 1.0f / s;
            if (m1 - m2 < TIE_THRESH) {
                int ix = atomicAdd(&g_fixn, 1);
                if (ix < FIXMAX) g_fixlist[ix] = r;
            }
        }
    }
}

// ---------------------------------------------------------------------------
// Kernel 1b: exact fp32 fixup for near-tie tokens (stride loop over list).
// ---------------------------------------------------------------------------
__global__ __launch_bounds__(64)
void fixup_kernel(const float* __restrict__ x,
                  const float* __restrict__ W,
                  int*   __restrict__ amax,
                  float* __restrict__ topp)
{
    __shared__ float xs[DK];
    __shared__ float ls[NE];

    int n = g_fixn; if (n > FIXMAX) n = FIXMAX;

    for (int idx = blockIdx.x; idx < n; idx += FIXGRID) {
        const int token = g_fixlist[idx];

        for (int i = threadIdx.x; i < DK / 4; i += 64)
            ((float4*)xs)[i] = ((const float4*)(x + (size_t)token * DK))[i];
        __syncthreads();

        const int e = threadIdx.x;               // 64 threads = 64 experts
        const float4* wr = (const float4*)(W + (size_t)e * DK);
        float a = 0.0f;
        #pragma unroll 8
        for (int i = 0; i < DK / 4; i++) {
            float4 w4 = wr[i];
            float4 x4 = ((const float4*)xs)[i];
            a = fmaf(x4.x, w4.x, a);
            a = fmaf(x4.y, w4.y, a);
            a = fmaf(x4.z, w4.z, a);
            a = fmaf(x4.w, w4.w, a);
        }
        ls[e] = a;
        __syncthreads();

        if (threadIdx.x == 0) {
            float mx = ls[0]; int mi = 0;
            for (int j = 1; j < NE; j++)
                if (ls[j] > mx) { mx = ls[j]; mi = j; }
            float s = 0.0f;
            for (int j = 0; j < NE; j++) s += __expf(ls[j] - mx);
            amax[token] = mi;
            topp[token] = 1.0f / s;
        }
        __syncthreads();
    }
}

// ---------------------------------------------------------------------------
// Kernel 2: warp-per-(batch,expert) capacity scan via ballot/popc, 256
// tokens per iteration. Also resets g_fixn for the next replay.
// ---------------------------------------------------------------------------
__global__ __launch_bounds__(256)
void scan_kernel(const int* __restrict__ amax, unsigned char* __restrict__ keep)
{
    if (blockIdx.x == 0 && threadIdx.x == 0) g_fixn = 0;

    const int gw   = blockIdx.x * 8 + (threadIdx.x >> 5);   // 0..255
    const int b    = gw >> 6;
    const int e    = gw & (NE - 1);
    const int lane = threadIdx.x & 31;
    const unsigned lmask_le = 0xffffffffu >> (31 - lane);

    const int* am = amax + (size_t)b * SEQ;
    unsigned char* kp = keep + (size_t)b * SEQ;

    int running = 0;
    for (int base = 0; base < SEQ; base += 256) {
        int v[8];
        #pragma unroll
        for (int k = 0; k < 8; k++) v[k] = am[base + lane + 32 * k];
        unsigned mk[8];
        #pragma unroll
        for (int k = 0; k < 8; k++) mk[k] = __ballot_sync(0xffffffffu, v[k] == e);
        #pragma unroll
        for (int k = 0; k < 8; k++) {
            if (v[k] == e)
                kp[base + lane + 32 * k] = (running + __popc(mk[k] & lmask_le) <= CAP);
            running += __popc(mk[k]);
        }
    }
}

// ---------------------------------------------------------------------------
// Kernel 3: scatter one-hot expert_indices and router_probs.
// ---------------------------------------------------------------------------
__global__ __launch_bounds__(256)
void scatter_kernel(const int* __restrict__ amax,
                    const unsigned char* __restrict__ keep,
                    const float* __restrict__ topp,
                    float* __restrict__ ei,
                    float* __restrict__ rp,
                    int M)
{
    const int token  = blockIdx.x * 16 + (threadIdx.x >> 4);
    const int lane16 = threadIdx.x & 15;
    if (token >= M) return;

    const int   am = amax[token];
    const float tp = topp[token];
    const int   kp = keep[token];

    float4 e = make_float4(0.f, 0.f, 0.f, 0.f);
    float4 r = make_float4(0.f, 0.f, 0.f, 0.f);
    const int c0 = lane16 * 4;
    if (kp && am >= c0 && am < c0 + 4) {
        ((float*)&e)[am - c0] = 1.0f;
        ((float*)&r)[am - c0] = tp;
    }
    *(float4*)&ei[(size_t)token * NE + c0] = e;
    *(float4*)&rp[(size_t)token * NE + c0] = r;
}

// ---------------------------------------------------------------------------
extern "C" void kernel_launch(void* const* d_in, const int* in_sizes, int n_in,
                              void* d_out, int out_size)
{
    const float* x = (const float*)d_in[0];
    const float* W = (const float*)d_in[1];
    (void)n_in; (void)out_size;

    const int M = in_sizes[0] / DK;          // B*S tokens (32768)
    const int B = M / SEQ;

    float* out = (float*)d_out;
    const size_t BSE = (size_t)M * NE;
    float* ei = out;                 // expert_indices (as float 0/1)
    float* rp = out + BSE;           // router_probs
    float* lg = out + 2 * BSE;       // logits

    int* amax;            cudaGetSymbolAddress((void**)&amax, g_argmax);
    float* topp;          cudaGetSymbolAddress((void**)&topp, g_topp);
    unsigned char* keep;  cudaGetSymbolAddress((void**)&keep, g_keep);

    cudaFuncSetAttribute(gemm_router_mma,
                         cudaFuncAttributeMaxDynamicSharedMemorySize, SMEM_REQ);

    prep_W<<<NCHUNK, 256>>>(W);
    gemm_router_mma<<<M / BM, 256, SMEM_REQ>>>(x, lg, amax, topp);
    fixup_kernel<<<FIXGRID, 64>>>(x, W, amax, topp);
    scan_kernel<<<(B * NE) / 8, 256>>>(amax, keep);
    scatter_kernel<<<(M + 15) / 16, 256>>>(amax, keep, topp, ei, rp, M);
}

// round 8
// speedup vs baseline: 1.1978x; 1.1978x over previous
#include <cuda_runtime.h>
#include <cuda_fp16.h>
#include <math.h>
#include <stdint.h>

// Problem constants (TopKRouter: B=4, S=8192, D=1024, E=64, top_k=1)
#define DK      1024
#define NE      64
#define SEQ     8192
#define CAP     640
#define MAXTOK  32768

// GEMM tiling: 256 threads = 8 warps; warp w owns rows [w*16, w*16+16) x all 64 cols
#define BM      128
#define KC      32            // K per chunk
#define NCHUNK  (DK / KC)     // 32
// smem (units = 4B half2):
#define SA 36                 // A row stride (16 kpairs + pad); 36 mod 32 = 4 -> conflict-free frags
#define SB 72                 // B kpair-row stride (64 + pad);  72 mod 32 = 8 -> conflict-free frags
#define A_WORDS   (BM * SA)             // 4608 per buffer
#define B_WORDS   ((KC / 2) * SB)       // 1152 per buffer
#define SMEM_REQ  ((2 * A_WORDS + 2 * B_WORDS) * 4)   // 46080 B

#define FIXMAX  1024
#define FIXGRID 256
#define TIE_THRESH 1e-4f

// Scratch (no allocations allowed -> __device__ globals)
__device__ int           g_argmax[MAXTOK];
__device__ float         g_topp[MAXTOK];
__device__ unsigned char g_keep[MAXTOK];
__device__ int           g_fixn;          // zero-init; reset by scan_kernel each run
__device__ int           g_fixlist[FIXMAX];

// pack two fp16 into u32
__device__ __forceinline__ uint32_t packh2(float x, float y) {
    __half2 h = __floats2half2_rn(x, y);
    return *(uint32_t*)&h;
}
// split pair (x,y) -> hi2 and lo2 packed fp16x2
__device__ __forceinline__ void split_pair(float x, float y, uint32_t& hi, uint32_t& lo) {
    float hx = __half2float(__float2half_rn(x));
    float hy = __half2float(__float2half_rn(y));
    hi = packh2(hx, hy);
    lo = packh2(x - hx, y - hy);
}
__device__ __forceinline__ void mma16(float* d,
                                      uint32_t a0, uint32_t a1, uint32_t a2, uint32_t a3,
                                      uint32_t b0, uint32_t b1) {
    asm volatile(
        "mma.sync.aligned.m16n8k16.row.col.f32.f16.f16.f32 "
        "{%0,%1,%2,%3}, {%4,%5,%6,%7}, {%8,%9}, {%0,%1,%2,%3};"
        : "+f"(d[0]), "+f"(d[1]), "+f"(d[2]), "+f"(d[3])
        : "r"(a0), "r"(a1), "r"(a2), "r"(a3), "r"(b0), "r"(b1));
}

// ---------------------------------------------------------------------------
// Kernel 1: logits = x @ W^T via mma.sync fp16 2-term-split (3 passes); fused
// top-1 softmax epilogue. Near-tie tokens queued for exact fp32 fixup.
// (R6 version — best measured GEMM: ~70us)
// ---------------------------------------------------------------------------
__global__ __launch_bounds__(256, 2)
void gemm_router_mma(const float* __restrict__ x,
                     const float* __restrict__ W,
                     float* __restrict__ logits,
                     int*   __restrict__ amax,
                     float* __restrict__ topp)
{
    extern __shared__ uint32_t smem[];
    uint32_t* Ah = smem;                    // [BM][SA] kpairs
    uint32_t* Al = Ah + A_WORDS;
    uint32_t* Bh = Al + A_WORDS;            // [KC/2][SB] : Bh[kpair][n]
    uint32_t* Bl = Bh + B_WORDS;

    const int tid  = threadIdx.x;
    const int wid  = tid >> 5;
    const int lane = tid & 31;
    const int l4   = lane >> 2;     // 0..7
    const int lc   = lane & 3;      // 0..3
    const int wm   = wid * 16;
    const int m0   = blockIdx.x * BM;

    // loader mapping
    const int arow = tid >> 3;      // 0..31 (rows arow+32q)
    const int ac4  = tid & 7;       // float4 index within 32-float chunk row

    const float* xb = x + (size_t)m0 * DK;

    float acc[8][4];
    #pragma unroll
    for (int j = 0; j < 8; j++)
        #pragma unroll
        for (int t = 0; t < 4; t++) acc[j][t] = 0.0f;

    // prefetch chunk 0
    float4 pa[4], pb[2];
    #pragma unroll
    for (int q = 0; q < 4; q++)
        pa[q] = *(const float4*)(xb + (size_t)(arow + 32 * q) * DK + ac4 * 4);
    #pragma unroll
    for (int q = 0; q < 2; q++)
        pb[q] = *(const float4*)(W + (size_t)(arow + 32 * q) * DK + ac4 * 4);

    for (int c = 0; c < NCHUNK; c++) {
        // ---- convert + STS ----
        #pragma unroll
        for (int q = 0; q < 4; q++) {
            const int row = arow + 32 * q;
            uint32_t h0, l0, h1, l1;
            split_pair(pa[q].x, pa[q].y, h0, l0);
            split_pair(pa[q].z, pa[q].w, h1, l1);
            const int ix = row * SA + ac4 * 2;
            *(uint2*)(Ah + ix) = make_uint2(h0, h1);
            *(uint2*)(Al + ix) = make_uint2(l0, l1);
        }
        #pragma unroll
        for (int q = 0; q < 2; q++) {
            const int n = arow + 32 * q;            // expert index 0..63
            uint32_t h0, l0, h1, l1;
            split_pair(pb[q].x, pb[q].y, h0, l0);
            split_pair(pb[q].z, pb[q].w, h1, l1);
            Bh[(ac4 * 2 + 0) * SB + n] = h0;
            Bh[(ac4 * 2 + 1) * SB + n] = h1;
            Bl[(ac4 * 2 + 0) * SB + n] = l0;
            Bl[(ac4 * 2 + 1) * SB + n] = l1;
        }
        __syncthreads();

        // prefetch next chunk (in flight during MMA phase)
        if (c + 1 < NCHUNK) {
            const int k0 = (c + 1) * KC;
            #pragma unroll
            for (int q = 0; q < 4; q++)
                pa[q] = *(const float4*)(xb + (size_t)(arow + 32 * q) * DK + k0 + ac4 * 4);
            #pragma unroll
            for (int q = 0; q < 2; q++)
                pb[q] = *(const float4*)(W + (size_t)(arow + 32 * q) * DK + k0 + ac4 * 4);
        }

        // ---- MMA: 2 k16-steps x 8 n-tiles x 3 passes ----
        #pragma unroll
        for (int ks = 0; ks < 2; ks++) {
            const int ko = ks * 8;
            const int ai = (wm + l4) * SA + ko + lc;
            uint32_t ah0 = Ah[ai],           ah1 = Ah[ai + 8 * SA];
            uint32_t ah2 = Ah[ai + 4],       ah3 = Ah[ai + 8 * SA + 4];
            uint32_t al0 = Al[ai],           al1 = Al[ai + 8 * SA];
            uint32_t al2 = Al[ai + 4],       al3 = Al[ai + 8 * SA + 4];
            const int bi = (ko + lc) * SB + l4;
            #pragma unroll
            for (int j = 0; j < 8; j++) {
                uint32_t bh0 = Bh[bi + j * 8], bh1 = Bh[bi + 4 * SB + j * 8];
                uint32_t bl0 = Bl[bi + j * 8], bl1 = Bl[bi + 4 * SB + j * 8];
                mma16(acc[j], ah0, ah1, ah2, ah3, bh0, bh1);  // hi*hi
                mma16(acc[j], ah0, ah1, ah2, ah3, bl0, bl1);  // hi*lo
                mma16(acc[j], al0, al1, al2, al3, bh0, bh1);  // lo*hi
            }
        }
        __syncthreads();
    }

    // ---- Epilogue: c0/c1 -> row wm+l4, c2/c3 -> row wm+l4+8; cols j*8+2lc(+1)
    #pragma unroll
    for (int half = 0; half < 2; half++) {
        const int r = m0 + wm + l4 + 8 * half;

        #pragma unroll
        for (int j = 0; j < 8; j++) {
            *(float2*)&logits[(size_t)r * NE + j * 8 + 2 * lc] =
                make_float2(acc[j][2 * half], acc[j][2 * half + 1]);
        }
        // local top1/top2 (+index)
        float m1 = -1e30f, m2 = -1e30f; int i1 = 0;
        #pragma unroll
        for (int j = 0; j < 8; j++)
            #pragma unroll
            for (int t = 0; t < 2; t++) {
                float v = acc[j][2 * half + t];
                int col = j * 8 + 2 * lc + t;
                if (v > m1) { m2 = m1; m1 = v; i1 = col; }
                else if (v > m2) m2 = v;
            }
        // quad merge (lanes sharing l4): offsets 1, 2
        #pragma unroll
        for (int off = 1; off <= 2; off <<= 1) {
            float om1 = __shfl_xor_sync(0xffffffffu, m1, off);
            int   oi1 = __shfl_xor_sync(0xffffffffu, i1, off);
            float om2 = __shfl_xor_sync(0xffffffffu, m2, off);
            if (om1 > m1 || (om1 == m1 && oi1 < i1)) {
                m2 = fmaxf(m1, om2); m1 = om1; i1 = oi1;
            } else {
                m2 = fmaxf(m2, om1);
            }
        }
        // softmax sum with converged max
        float s = 0.0f;
        #pragma unroll
        for (int j = 0; j < 8; j++)
            #pragma unroll
            for (int t = 0; t < 2; t++)
                s += __expf(acc[j][2 * half + t] - m1);
        s += __shfl_xor_sync(0xffffffffu, s, 1);
        s += __shfl_xor_sync(0xffffffffu, s, 2);

        if (lc == 0) {
            amax[r] = i1;
            topp[r] = 1.0f / s;
            if (m1 - m2 < TIE_THRESH) {
                int ix = atomicAdd(&g_fixn, 1);
                if (ix < FIXMAX) g_fixlist[ix] = r;
            }
        }
    }
}

// ---------------------------------------------------------------------------
// Kernel 1b: exact fp32 fixup for near-tie tokens (stride loop over list).
// ---------------------------------------------------------------------------
__global__ __launch_bounds__(64)
void fixup_kernel(const float* __restrict__ x,
                  const float* __restrict__ W,
                  int*   __restrict__ amax,
                  float* __restrict__ topp)
{
    __shared__ float xs[DK];
    __shared__ float ls[NE];

    int n = g_fixn; if (n > FIXMAX) n = FIXMAX;

    for (int idx = blockIdx.x; idx < n; idx += FIXGRID) {
        const int token = g_fixlist[idx];

        for (int i = threadIdx.x; i < DK / 4; i += 64)
            ((float4*)xs)[i] = ((const float4*)(x + (size_t)token * DK))[i];
        __syncthreads();

        const int e = threadIdx.x;               // 64 threads = 64 experts
        const float4* wr = (const float4*)(W + (size_t)e * DK);
        float a = 0.0f;
        #pragma unroll 8
        for (int i = 0; i < DK / 4; i++) {
            float4 w4 = wr[i];
            float4 x4 = ((const float4*)xs)[i];
            a = fmaf(x4.x, w4.x, a);
            a = fmaf(x4.y, w4.y, a);
            a = fmaf(x4.z, w4.z, a);
            a = fmaf(x4.w, w4.w, a);
        }
        ls[e] = a;
        __syncthreads();

        if (threadIdx.x == 0) {
            float mx = ls[0]; int mi = 0;
            for (int j = 1; j < NE; j++)
                if (ls[j] > mx) { mx = ls[j]; mi = j; }
            float s = 0.0f;
            for (int j = 0; j < NE; j++) s += __expf(ls[j] - mx);
            amax[token] = mi;
            topp[token] = 1.0f / s;
        }
        __syncthreads();
    }
}

// ---------------------------------------------------------------------------
// Kernel 2: capacity scan, block per (b,e), 8 warps x 1024-token segments.
// Pass 1: per-segment match counts. Prefix in smem. Pass 2: emit keep flags.
// 2048 concurrent warps (vs 256 before) -> latency hidden.
// Also resets g_fixn for the next graph replay (runs after fixup).
// ---------------------------------------------------------------------------
#define SEG 1024
__global__ __launch_bounds__(256)
void scan_kernel(const int* __restrict__ amax, unsigned char* __restrict__ keep)
{
    if (blockIdx.x == 0 && threadIdx.x == 0) g_fixn = 0;

    const int b    = blockIdx.x >> 6;
    const int e    = blockIdx.x & (NE - 1);
    const int w    = threadIdx.x >> 5;          // segment 0..7
    const int lane = threadIdx.x & 31;
    const unsigned lmask_le = 0xffffffffu >> (31 - lane);

    const int* am = amax + (size_t)b * SEQ + w * SEG;
    unsigned char* kp = keep + (size_t)b * SEQ + w * SEG;

    __shared__ int segcnt[8];

    // ---- pass 1: count matches in this warp's segment ----
    int cnt = 0;
    #pragma unroll
    for (int base = 0; base < SEG; base += 128) {
        int v0 = am[base + lane];
        int v1 = am[base + lane + 32];
        int v2 = am[base + lane + 64];
        int v3 = am[base + lane + 96];
        cnt += __popc(__ballot_sync(0xffffffffu, v0 == e));
        cnt += __popc(__ballot_sync(0xffffffffu, v1 == e));
        cnt += __popc(__ballot_sync(0xffffffffu, v2 == e));
        cnt += __popc(__ballot_sync(0xffffffffu, v3 == e));
    }
    if (lane == 0) segcnt[w] = cnt;
    __syncthreads();

    // exclusive prefix of earlier segments
    int running = 0;
    #pragma unroll
    for (int q = 0; q < 8; q++)
        if (q < w) running += segcnt[q];

    // ---- pass 2: emit (L1-hot re-read of own 4KB) ----
    #pragma unroll
    for (int base = 0; base < SEG; base += 128) {
        int v0 = am[base + lane];
        int v1 = am[base + lane + 32];
        int v2 = am[base + lane + 64];
        int v3 = am[base + lane + 96];
        unsigned m0 = __ballot_sync(0xffffffffu, v0 == e);
        unsigned m1 = __ballot_sync(0xffffffffu, v1 == e);
        unsigned m2 = __ballot_sync(0xffffffffu, v2 == e);
        unsigned m3 = __ballot_sync(0xffffffffu, v3 == e);
        if (v0 == e) kp[base + lane]      = (running + __popc(m0 & lmask_le) <= CAP);
        running += __popc(m0);
        if (v1 == e) kp[base + lane + 32] = (running + __popc(m1 & lmask_le) <= CAP);
        running += __popc(m1);
        if (v2 == e) kp[base + lane + 64] = (running + __popc(m2 & lmask_le) <= CAP);
        running += __popc(m2);
        if (v3 == e) kp[base + lane + 96] = (running + __popc(m3 & lmask_le) <= CAP);
        running += __popc(m3);
    }
}

// ---------------------------------------------------------------------------
// Kernel 3: scatter one-hot expert_indices and router_probs.
// ---------------------------------------------------------------------------
__global__ __launch_bounds__(256)
void scatter_kernel(const int* __restrict__ amax,
                    const unsigned char* __restrict__ keep,
                    const float* __restrict__ topp,
                    float* __restrict__ ei,
                    float* __restrict__ rp,
                    int M)
{
    const int token  = blockIdx.x * 16 + (threadIdx.x >> 4);
    const int lane16 = threadIdx.x & 15;
    if (token >= M) return;

    const int   am = amax[token];
    const float tp = topp[token];
    const int   kp = keep[token];

    float4 e = make_float4(0.f, 0.f, 0.f, 0.f);
    float4 r = make_float4(0.f, 0.f, 0.f, 0.f);
    const int c0 = lane16 * 4;
    if (kp && am >= c0 && am < c0 + 4) {
        ((float*)&e)[am - c0] = 1.0f;
        ((float*)&r)[am - c0] = tp;
    }
    *(float4*)&ei[(size_t)token * NE + c0] = e;
    *(float4*)&rp[(size_t)token * NE + c0] = r;
}

// ---------------------------------------------------------------------------
extern "C" void kernel_launch(void* const* d_in, const int* in_sizes, int n_in,
                              void* d_out, int out_size)
{
    const float* x = (const float*)d_in[0];
    const float* W = (const float*)d_in[1];
    (void)n_in; (void)out_size;

    const int M = in_sizes[0] / DK;          // B*S tokens (32768)
    const int B = M / SEQ;

    float* out = (float*)d_out;
    const size_t BSE = (size_t)M * NE;
    float* ei = out;                 // expert_indices (as float 0/1)
    float* rp = out + BSE;           // router_probs
    float* lg = out + 2 * BSE;       // logits

    int* amax;            cudaGetSymbolAddress((void**)&amax, g_argmax);
    float* topp;          cudaGetSymbolAddress((void**)&topp, g_topp);
    unsigned char* keep;  cudaGetSymbolAddress((void**)&keep, g_keep);

    cudaFuncSetAttribute(gemm_router_mma,
                         cudaFuncAttributeMaxDynamicSharedMemorySize, SMEM_REQ);

    gemm_router_mma<<<M / BM, 256, SMEM_REQ>>>(x, W, lg, amax, topp);
    fixup_kernel<<<FIXGRID, 64>>>(x, W, amax, topp);
    scan_kernel<<<B * NE, 256>>>(amax, keep);
    scatter_kernel<<<(M + 15) / 16, 256>>>(amax, keep, topp, ei, rp, M);
}